// round 9
// baseline (speedup 1.0000x reference)
#include <cuda_runtime.h>

// y[..., 2k]   = T[k,0,0]*x[2k] + T[k,0,1]*x[2k+1]
// y[..., 2k+1] = T[k,1,0]*x[2k] + T[k,1,1]*x[2k+1]
// x: (8192 rows, 4096 floats) fp32, twiddle: (2048, 2, 2) fp32 (32 KiB).
//
// Persistent single-wave grid: 512 blocks (< 148 SMs x 4 CTA slots at 60
// regs), each block owns one column half (2048 floats) of 32 contiguous
// rows. Twiddle loaded ONCE per thread into registers and reused 32x.
// Steady state: 1 LDG.256 + 8 FMA + 1 STG.256 per row-iteration, 4-deep
// load batching for MLP. One wave -> no wave transitions, no tail.

struct f8 { float v[8]; };

__device__ __forceinline__ f8 ldg256_stream(const float* p) {
    f8 r;
    asm volatile("ld.global.nc.L2::evict_first.v8.b32 "
                 "{%0,%1,%2,%3,%4,%5,%6,%7}, [%8];"
                 : "=f"(r.v[0]), "=f"(r.v[1]), "=f"(r.v[2]), "=f"(r.v[3]),
                   "=f"(r.v[4]), "=f"(r.v[5]), "=f"(r.v[6]), "=f"(r.v[7])
                 : "l"(p));
    return r;
}

__device__ __forceinline__ f8 ldg256_cached(const float* p) {
    f8 r;
    asm volatile("ld.global.nc.v8.b32 "
                 "{%0,%1,%2,%3,%4,%5,%6,%7}, [%8];"
                 : "=f"(r.v[0]), "=f"(r.v[1]), "=f"(r.v[2]), "=f"(r.v[3]),
                   "=f"(r.v[4]), "=f"(r.v[5]), "=f"(r.v[6]), "=f"(r.v[7])
                 : "l"(p));
    return r;
}

__device__ __forceinline__ void stg256_stream(float* p, const f8& r) {
    asm volatile("st.global.L2::evict_first.v8.b32 "
                 "[%0], {%1,%2,%3,%4,%5,%6,%7,%8};"
                 :: "l"(p),
                    "f"(r.v[0]), "f"(r.v[1]), "f"(r.v[2]), "f"(r.v[3]),
                    "f"(r.v[4]), "f"(r.v[5]), "f"(r.v[6]), "f"(r.v[7])
                 : "memory");
}

static constexpr int ROW_FLOATS     = 4096;
static constexpr int NUM_BLOCKS     = 512;   // single wave (148 SMs x 4 CTAs)
static constexpr int ROWS_PER_BLOCK = 32;    // 8192 rows / (512/2 row-groups)
static constexpr int BATCH          = 4;

__global__ __launch_bounds__(256) void butterfly_kernel(
    const float* __restrict__ x,
    const float* __restrict__ tw,
    float* __restrict__ y)
{
    // blockIdx.x = row_group * 2 + column_half; 256 row groups of 32 rows.
    const int half  = blockIdx.x & 1;
    const int grp   = blockIdx.x >> 1;
    const int chunk = (half << 8) + threadIdx.x;   // 0..511, 8 floats each
    const int col   = chunk << 3;

    // Twiddle for this thread's 4 pairs, loaded once, reused for 32 rows.
    const f8 ta = ldg256_cached(&tw[chunk << 4]);
    const f8 tb = ldg256_cached(&tw[(chunk << 4) + 8]);

    const long base = (long)grp * ROWS_PER_BLOCK * ROW_FLOATS + col;

    for (int r0 = 0; r0 < ROWS_PER_BLOCK; r0 += BATCH) {
        f8 v[BATCH];
        // Front-batch 4 independent 256-bit loads (deep MLP); these issue
        // while the previous iteration's stores are still draining.
#pragma unroll
        for (int u = 0; u < BATCH; u++)
            v[u] = ldg256_stream(&x[base + (long)(r0 + u) * ROW_FLOATS]);

#pragma unroll
        for (int u = 0; u < BATCH; u++) {
            f8 o;
            o.v[0] = fmaf(ta.v[0], v[u].v[0], ta.v[1] * v[u].v[1]);
            o.v[1] = fmaf(ta.v[2], v[u].v[0], ta.v[3] * v[u].v[1]);
            o.v[2] = fmaf(ta.v[4], v[u].v[2], ta.v[5] * v[u].v[3]);
            o.v[3] = fmaf(ta.v[6], v[u].v[2], ta.v[7] * v[u].v[3]);
            o.v[4] = fmaf(tb.v[0], v[u].v[4], tb.v[1] * v[u].v[5]);
            o.v[5] = fmaf(tb.v[2], v[u].v[4], tb.v[3] * v[u].v[5]);
            o.v[6] = fmaf(tb.v[4], v[u].v[6], tb.v[5] * v[u].v[7]);
            o.v[7] = fmaf(tb.v[6], v[u].v[6], tb.v[7] * v[u].v[7]);
            stg256_stream(&y[base + (long)(r0 + u) * ROW_FLOATS], o);
        }
    }
}

extern "C" void kernel_launch(void* const* d_in, const int* in_sizes, int n_in,
                              void* d_out, int out_size)
{
    const float* x  = (const float*)d_in[0];
    const float* tw = (const float*)d_in[1];
    float* y        = (float*)d_out;

    butterfly_kernel<<<NUM_BLOCKS, 256>>>(x, tw, y);
}

// round 10
// speedup vs baseline: 1.1176x; 1.1176x over previous
#include <cuda_runtime.h>

// y[..., 2k]   = T[k,0,0]*x[2k] + T[k,0,1]*x[2k+1]
// y[..., 2k+1] = T[k,1,0]*x[2k] + T[k,1,1]*x[2k+1]
// x: (8192 rows, 4096 floats) fp32, twiddle: (2048, 2, 2) fp32 (32 KiB).
//
// DRAM-floor kernel body (register twiddle, 256-bit LDG/STG, front-batched
// loads) at the grid granularity that minimizes wall-clock overhead:
// ROWS_PER_BLOCK=2 -> 8192 blocks (finest gap observed: ~6.4us).

struct f8 { float v[8]; };

__device__ __forceinline__ f8 ldg256_stream(const float* p) {
    f8 r;
    asm volatile("ld.global.nc.L2::evict_first.v8.b32 "
                 "{%0,%1,%2,%3,%4,%5,%6,%7}, [%8];"
                 : "=f"(r.v[0]), "=f"(r.v[1]), "=f"(r.v[2]), "=f"(r.v[3]),
                   "=f"(r.v[4]), "=f"(r.v[5]), "=f"(r.v[6]), "=f"(r.v[7])
                 : "l"(p));
    return r;
}

__device__ __forceinline__ f8 ldg256_cached(const float* p) {
    f8 r;
    asm volatile("ld.global.nc.v8.b32 "
                 "{%0,%1,%2,%3,%4,%5,%6,%7}, [%8];"
                 : "=f"(r.v[0]), "=f"(r.v[1]), "=f"(r.v[2]), "=f"(r.v[3]),
                   "=f"(r.v[4]), "=f"(r.v[5]), "=f"(r.v[6]), "=f"(r.v[7])
                 : "l"(p));
    return r;
}

__device__ __forceinline__ void stg256_stream(float* p, const f8& r) {
    asm volatile("st.global.L2::evict_first.v8.b32 "
                 "[%0], {%1,%2,%3,%4,%5,%6,%7,%8};"
                 :: "l"(p),
                    "f"(r.v[0]), "f"(r.v[1]), "f"(r.v[2]), "f"(r.v[3]),
                    "f"(r.v[4]), "f"(r.v[5]), "f"(r.v[6]), "f"(r.v[7])
                 : "memory");
}

static constexpr int ROW_FLOATS     = 4096;
static constexpr int ROWS_PER_BLOCK = 2;

__global__ __launch_bounds__(256) void butterfly_kernel(
    const float* __restrict__ x,
    const float* __restrict__ tw,
    float* __restrict__ y)
{
    // blockIdx.x = row_group * 2 + column_half; 4096 row groups of 2 rows.
    const int half  = blockIdx.x & 1;
    const int grp   = blockIdx.x >> 1;
    const int chunk = (half << 8) + threadIdx.x;   // 0..511, 8 floats each
    const int col   = chunk << 3;

    const long base = (long)grp * ROWS_PER_BLOCK * ROW_FLOATS + col;

    // Front-batch ALL independent loads: 2 streaming x rows + 2 twiddle.
    f8 v0 = ldg256_stream(&x[base]);
    f8 v1 = ldg256_stream(&x[base + ROW_FLOATS]);
    const f8 ta = ldg256_cached(&tw[chunk << 4]);
    const f8 tb = ldg256_cached(&tw[(chunk << 4) + 8]);

    f8 o;
    o.v[0] = fmaf(ta.v[0], v0.v[0], ta.v[1] * v0.v[1]);
    o.v[1] = fmaf(ta.v[2], v0.v[0], ta.v[3] * v0.v[1]);
    o.v[2] = fmaf(ta.v[4], v0.v[2], ta.v[5] * v0.v[3]);
    o.v[3] = fmaf(ta.v[6], v0.v[2], ta.v[7] * v0.v[3]);
    o.v[4] = fmaf(tb.v[0], v0.v[4], tb.v[1] * v0.v[5]);
    o.v[5] = fmaf(tb.v[2], v0.v[4], tb.v[3] * v0.v[5]);
    o.v[6] = fmaf(tb.v[4], v0.v[6], tb.v[5] * v0.v[7]);
    o.v[7] = fmaf(tb.v[6], v0.v[6], tb.v[7] * v0.v[7]);
    stg256_stream(&y[base], o);

    o.v[0] = fmaf(ta.v[0], v1.v[0], ta.v[1] * v1.v[1]);
    o.v[1] = fmaf(ta.v[2], v1.v[0], ta.v[3] * v1.v[1]);
    o.v[2] = fmaf(ta.v[4], v1.v[2], ta.v[5] * v1.v[3]);
    o.v[3] = fmaf(ta.v[6], v1.v[2], ta.v[7] * v1.v[3]);
    o.v[4] = fmaf(tb.v[0], v1.v[4], tb.v[1] * v1.v[5]);
    o.v[5] = fmaf(tb.v[2], v1.v[4], tb.v[3] * v1.v[5]);
    o.v[6] = fmaf(tb.v[4], v1.v[6], tb.v[5] * v1.v[7]);
    o.v[7] = fmaf(tb.v[6], v1.v[6], tb.v[7] * v1.v[7]);
    stg256_stream(&y[base + ROW_FLOATS], o);
}

extern "C" void kernel_launch(void* const* d_in, const int* in_sizes, int n_in,
                              void* d_out, int out_size)
{
    const float* x  = (const float*)d_in[0];
    const float* tw = (const float*)d_in[1];
    float* y        = (float*)d_out;

    const int rows   = out_size / ROW_FLOATS;                 // 8192
    const int blocks = (rows / ROWS_PER_BLOCK) * 2;           // 8192

    butterfly_kernel<<<blocks, 256>>>(x, tw, y);
}

// round 12
// speedup vs baseline: 1.1316x; 1.0125x over previous
#include <cuda_runtime.h>

// y[..., 2k]   = T[k,0,0]*x[2k] + T[k,0,1]*x[2k+1]
// y[..., 2k+1] = T[k,1,0]*x[2k] + T[k,1,1]*x[2k+1]
// x: (8192 rows, 4096 floats) fp32, twiddle: (2048, 2, 2) fp32 (32 KiB).
//
// Converged config: DRAM-floor body (register-resident twiddle, 256-bit
// LDG/STG, front-batched loads), ROWS_PER_BLOCK=4 -> 4096 blocks (best
// measured harness time). Twiddle loads issued first (L1/L2-fast, frees
// scoreboard) and pinned with evict_last; x/y stream with evict_first.

struct f8 { float v[8]; };

__device__ __forceinline__ f8 ldg256_stream(const float* p) {
    f8 r;
    asm volatile("ld.global.nc.L2::evict_first.v8.b32 "
                 "{%0,%1,%2,%3,%4,%5,%6,%7}, [%8];"
                 : "=f"(r.v[0]), "=f"(r.v[1]), "=f"(r.v[2]), "=f"(r.v[3]),
                   "=f"(r.v[4]), "=f"(r.v[5]), "=f"(r.v[6]), "=f"(r.v[7])
                 : "l"(p));
    return r;
}

__device__ __forceinline__ f8 ldg256_pin(const float* p) {
    f8 r;
    asm volatile("ld.global.nc.L2::evict_last.v8.b32 "
                 "{%0,%1,%2,%3,%4,%5,%6,%7}, [%8];"
                 : "=f"(r.v[0]), "=f"(r.v[1]), "=f"(r.v[2]), "=f"(r.v[3]),
                   "=f"(r.v[4]), "=f"(r.v[5]), "=f"(r.v[6]), "=f"(r.v[7])
                 : "l"(p));
    return r;
}

__device__ __forceinline__ void stg256_stream(float* p, const f8& r) {
    asm volatile("st.global.L2::evict_first.v8.b32 "
                 "[%0], {%1,%2,%3,%4,%5,%6,%7,%8};"
                 :: "l"(p),
                    "f"(r.v[0]), "f"(r.v[1]), "f"(r.v[2]), "f"(r.v[3]),
                    "f"(r.v[4]), "f"(r.v[5]), "f"(r.v[6]), "f"(r.v[7])
                 : "memory");
}

static constexpr int ROW_FLOATS     = 4096;
static constexpr int ROWS_PER_BLOCK = 4;

__global__ __launch_bounds__(256) void butterfly_kernel(
    const float* __restrict__ x,
    const float* __restrict__ tw,
    float* __restrict__ y)
{
    // blockIdx.x = row_group * 2 + column_half; 2048 row groups of 4 rows.
    const int half  = blockIdx.x & 1;
    const int grp   = blockIdx.x >> 1;
    const int chunk = (half << 8) + threadIdx.x;   // 0..511, 8 floats each
    const int col   = chunk << 3;

    // Twiddle first: L1/L2-fast, scoreboard frees early. Pinned in L2.
    const f8 ta = ldg256_pin(&tw[chunk << 4]);
    const f8 tb = ldg256_pin(&tw[(chunk << 4) + 8]);

    const long base = (long)grp * ROWS_PER_BLOCK * ROW_FLOATS + col;

    f8 v[ROWS_PER_BLOCK];
    // 4 independent streaming 256-bit loads: the only long-latency waits.
#pragma unroll
    for (int u = 0; u < ROWS_PER_BLOCK; u++)
        v[u] = ldg256_stream(&x[base + (long)u * ROW_FLOATS]);

#pragma unroll
    for (int u = 0; u < ROWS_PER_BLOCK; u++) {
        f8 o;
        o.v[0] = fmaf(ta.v[0], v[u].v[0], ta.v[1] * v[u].v[1]);
        o.v[1] = fmaf(ta.v[2], v[u].v[0], ta.v[3] * v[u].v[1]);
        o.v[2] = fmaf(ta.v[4], v[u].v[2], ta.v[5] * v[u].v[3]);
        o.v[3] = fmaf(ta.v[6], v[u].v[2], ta.v[7] * v[u].v[3]);
        o.v[4] = fmaf(tb.v[0], v[u].v[4], tb.v[1] * v[u].v[5]);
        o.v[5] = fmaf(tb.v[2], v[u].v[4], tb.v[3] * v[u].v[5]);
        o.v[6] = fmaf(tb.v[4], v[u].v[6], tb.v[5] * v[u].v[7]);
        o.v[7] = fmaf(tb.v[6], v[u].v[6], tb.v[7] * v[u].v[7]);
        stg256_stream(&y[base + (long)u * ROW_FLOATS], o);
    }
}

extern "C" void kernel_launch(void* const* d_in, const int* in_sizes, int n_in,
                              void* d_out, int out_size)
{
    const float* x  = (const float*)d_in[0];
    const float* tw = (const float*)d_in[1];
    float* y        = (float*)d_out;

    const int rows   = out_size / ROW_FLOATS;            // 8192
    const int blocks = (rows / ROWS_PER_BLOCK) * 2;      // 4096

    butterfly_kernel<<<blocks, 256>>>(x, tw, y);
}